// round 8
// baseline (speedup 1.0000x reference)
#include <cuda_runtime.h>
#include <cstdint>

#define N     8192
#define K1    31
#define CAP   256      // per-row candidate capacity (mean 88, max ~135)
#define CCAP  176      // per-column smem list capacity (max ~144 at +6 sigma)
#define PIVOT 2.3f     // P(z>2.3)=0.0107
#define NF4   ((size_t)N * N / 4)
#define FULLM 0xFFFFFFFFu

__device__ unsigned int       g_bits[(size_t)N * N / 32];  // 8 MB candidate bitmask
__device__ unsigned long long g_colth[N];

// Monotone map float -> uint32 (larger float => larger key)
__device__ __forceinline__ unsigned int fkey(float x) {
    unsigned int u = __float_as_uint(x);
    return (u & 0x80000000u) ? ~u : (u | 0x80000000u);
}
__device__ __forceinline__ float inv_fkey(unsigned int k) {
    unsigned int u = (k & 0x80000000u) ? (k ^ 0x80000000u) : ~k;
    return __uint_as_float(u);
}
// Composite key: value-major, lower index wins ties (stable top_k semantics)
__device__ __forceinline__ unsigned long long ckey(float x, int idx) {
    return ((unsigned long long)fkey(x) << 32) | (unsigned int)(N - 1 - idx);
}

__device__ __forceinline__ unsigned long long warp_max(unsigned long long v) {
#pragma unroll
    for (int o = 16; o > 0; o >>= 1) {
        unsigned long long w = __shfl_xor_sync(FULLM, v, o);
        if (w > v) v = w;
    }
    return v;
}

// warp-level exact fallback for a COLUMN (never triggered statistically)
__device__ unsigned long long warp_fallback_col(const float* __restrict__ A, int j, int lane) {
    unsigned long long prev = 0xFFFFFFFFFFFFFFFFull;
    for (int it = 0; it < K1; it++) {
        unsigned long long best = 0;
        for (int t = lane; t < N; t += 32) {
            unsigned long long k = ckey(A[(size_t)t * N + j], t);
            if (k < prev && k > best) best = k;
        }
        prev = warp_max(best);
    }
    return prev;
}

// block-level exact fallback for a ROW (never triggered statistically)
__device__ unsigned long long block_fallback_row(const float* __restrict__ A, int i) {
    __shared__ unsigned long long red[256];
    unsigned long long prev = 0xFFFFFFFFFFFFFFFFull;
    for (int it = 0; it < K1; it++) {
        unsigned long long best = 0;
        for (int t = threadIdx.x; t < N; t += 256) {
            unsigned long long k = ckey(A[(size_t)i * N + t], t);
            if (k < prev && k > best) best = k;
        }
        red[threadIdx.x] = best;
        __syncthreads();
        for (int s = 128; s > 0; s >>= 1) {
            if (threadIdx.x < s) {
                unsigned long long o = red[threadIdx.x + s];
                if (o > red[threadIdx.x]) red[threadIdx.x] = o;
            }
            __syncthreads();
        }
        prev = red[0];
        __syncthreads();
    }
    return prev;
}

// K1: PURE streaming pass (measured 81us @ 6.1TB/s). Reads A, zeros out,
// emits bitmask via ballots. Word i*256+seg*4+comp, bit b <-> (i, seg*128+b*4+comp).
__global__ __launch_bounds__(256) void stream_kernel(const float* __restrict__ A,
                                                     float* __restrict__ out) {
    const size_t g = (size_t)blockIdx.x * 256 + threadIdx.x;  // float4 index
    float4 v = ((const float4*)A)[g];
    const float4 zz = {0.0f, 0.0f, 0.0f, 0.0f};
    ((float4*)out)[g] = zz;
    unsigned m0 = __ballot_sync(FULLM, v.x > PIVOT);
    unsigned m1 = __ballot_sync(FULLM, v.y > PIVOT);
    unsigned m2 = __ballot_sync(FULLM, v.z > PIVOT);
    unsigned m3 = __ballot_sync(FULLM, v.w > PIVOT);
    if ((threadIdx.x & 31) == 0) {
        uint4 w = {m0, m1, m2, m3};
        ((uint4*)g_bits)[g >> 5] = w;
    }
}

// K2: column thresholds. CTA cb handles the 32 columns of word-column
// (seg=cb>>2, comp=cb&3). Per-column lists live in SMEM; no global atomics.
__global__ __launch_bounds__(256) void colth_kernel(const float* __restrict__ A) {
    const int cb = blockIdx.x, seg = cb >> 2, comp = cb & 3;
    const int t = threadIdx.x, lane = t & 31, w = t >> 5;
    __shared__ unsigned long long keys[32][CCAP];   // 45 KB
    __shared__ int cnt[32];
    if (t < 32) cnt[t] = 0;
    __syncthreads();

    // front-batch the 32 word loads (rows t, t+256, ...)
    unsigned wrd[32];
#pragma unroll
    for (int k = 0; k < 32; k++)
        wrd[k] = g_bits[(size_t)(t + 256 * k) * 256 + seg * 4 + comp];

#pragma unroll
    for (int k = 0; k < 32; k++) {
        unsigned wb = wrd[k];
        const int r = t + 256 * k;
        while (wb) {
            int b = __ffs(wb) - 1;
            wb &= wb - 1;
            int j = seg * 128 + b * 4 + comp;
            float x = A[(size_t)r * N + j];
            int cs = atomicAdd(&cnt[b], 1);
            if (cs < CCAP) keys[b][cs] = ckey(x, r);
        }
    }
    __syncthreads();

    // warp w ranks columns b = 4w .. 4w+3
#pragma unroll
    for (int q = 0; q < 4; q++) {
        const int b = w * 4 + q;
        const int j = seg * 128 + b * 4 + comp;
        const int c = cnt[b];
        if (c >= K1 && c <= CCAP) {
            unsigned long long kq[6];
            int rk[6];
#pragma unroll
            for (int m = 0; m < 6; m++) {
                int s = lane + 32 * m;
                kq[m] = (s < c) ? keys[b][s] : 0ull;
                rk[m] = 0;
            }
            for (int idx = 0; idx < c; idx++) {
                unsigned long long km = keys[b][idx];  // LDS broadcast
#pragma unroll
                for (int m = 0; m < 6; m++) rk[m] += (km > kq[m]);
            }
            unsigned long long th = 0;
#pragma unroll
            for (int m = 0; m < 6; m++)
                if (lane + 32 * m < c && rk[m] == K1 - 1) th = kq[m];
            th = warp_max(th);
            if (lane == 0) g_colth[j] = th;
        } else {
            unsigned long long th = warp_fallback_col(A, j, lane);
            if (lane == 0) g_colth[j] = th;
        }
    }
}

// K3: block per row. Decode bits -> gather candidates -> rowth (local) ->
// scatter survivors against g_colth. No global atomics, 3 barriers.
__global__ __launch_bounds__(256) void rowscat_kernel(const float* __restrict__ A,
                                                      float* __restrict__ out) {
    const int i = blockIdx.x, t = threadIdx.x, lane = t & 31, w = t >> 5;
    __shared__ unsigned long long keys[CAP];
    __shared__ int wsum[8];
    __shared__ int s_total;
    __shared__ unsigned long long s_rowth;

    unsigned wrd = g_bits[(size_t)i * 256 + t];
    int cnt = __popc(wrd);
    int off = cnt;
#pragma unroll
    for (int d = 1; d < 32; d <<= 1) {
        int v = __shfl_up_sync(FULLM, off, d);
        if (lane >= d) off += v;
    }
    if (lane == 31) wsum[w] = off;
    __syncthreads();
    if (t == 0) {
        int s = 0;
#pragma unroll
        for (int k = 0; k < 8; k++) { int v = wsum[k]; wsum[k] = s; s += v; }
        s_total = s;
    }
    __syncthreads();
    const int total = s_total;
    off += wsum[w] - cnt;   // exclusive global offset

    if (total >= K1 && total <= CAP) {
        unsigned wb = wrd;
        const int seg = t >> 2, comp = t & 3;
        int o = off;
        while (wb) {
            int b = __ffs(wb) - 1;
            wb &= wb - 1;
            int j = seg * 128 + b * 4 + comp;
            keys[o++] = ckey(A[(size_t)i * N + j], j);
        }
        __syncthreads();
        for (int s = t; s < total; s += 256) {
            unsigned long long kt = keys[s];
            int r = 0;
            for (int m = 0; m < total; m++) r += (keys[m] > kt);
            if (r == K1 - 1) s_rowth = kt;
        }
        __syncthreads();
        const unsigned long long rth = s_rowth;
        for (int s = t; s < total; s += 256) {
            unsigned long long k = keys[s];
            if (k < rth) continue;
            int j = N - 1 - (int)(unsigned int)(k & 0xFFFFFFFFu);
            if (j == i) continue;
            float x = inv_fkey((unsigned int)(k >> 32));
            if (ckey(x, i) >= g_colth[j])
                out[(size_t)i * N + j] = x;
        }
    } else {
        // exact rowth + full-row rescan (covers values <= PIVOT too)
        unsigned long long rth = block_fallback_row(A, i);
        for (int j = t; j < N; j += 256) {
            if (j == i) continue;
            float x = A[(size_t)i * N + j];
            if (ckey(x, j) >= rth && ckey(x, i) >= g_colth[j])
                out[(size_t)i * N + j] = x;
        }
    }
}

extern "C" void kernel_launch(void* const* d_in, const int* in_sizes, int n_in,
                              void* d_out, int out_size) {
    const float* A = (const float*)d_in[0];
    float* out = (float*)d_out;
    stream_kernel<<<(unsigned)(NF4 / 256), 256>>>(A, out);
    colth_kernel<<<256, 256>>>(A);
    rowscat_kernel<<<N, 256>>>(A, out);
}

// round 9
// speedup vs baseline: 1.5188x; 1.5188x over previous
#include <cuda_runtime.h>
#include <cstdint>

#define N     8192
#define K1    31
#define CAP   256      // per-line candidate capacity (mean 88, max ~135)
#define PIVOT 2.3f     // P(z>2.3)=0.0107
#define NF4   ((size_t)N * N / 4)
#define FULLM 0xFFFFFFFFu

__device__ unsigned int       g_bits[(size_t)N * N / 32];  // 8 MB candidate bitmask
__device__ unsigned long long g_colcand[(size_t)N * CAP];  // 16 MB
__device__ int                g_colcnt[N];
__device__ unsigned long long g_rowth[N];

// Monotone map float -> uint32 (larger float => larger key)
__device__ __forceinline__ unsigned int fkey(float x) {
    unsigned int u = __float_as_uint(x);
    return (u & 0x80000000u) ? ~u : (u | 0x80000000u);
}
__device__ __forceinline__ float inv_fkey(unsigned int k) {
    unsigned int u = (k & 0x80000000u) ? (k ^ 0x80000000u) : ~k;
    return __uint_as_float(u);
}
// Composite key: value-major, lower index wins ties (stable top_k semantics)
__device__ __forceinline__ unsigned long long ckey(float x, int idx) {
    return ((unsigned long long)fkey(x) << 32) | (unsigned int)(N - 1 - idx);
}

// block-level exact fallback: K1-th largest key of a full line (never
// triggered statistically; kept for exactness on arbitrary inputs)
template <bool ROW, int BT>
__device__ unsigned long long block_fallback(const float* __restrict__ A, int line) {
    __shared__ unsigned long long red[BT];
    unsigned long long prev = 0xFFFFFFFFFFFFFFFFull;
    for (int it = 0; it < K1; it++) {
        unsigned long long best = 0;
        for (int t = threadIdx.x; t < N; t += BT) {
            float x = ROW ? A[(size_t)line * N + t] : A[(size_t)t * N + line];
            unsigned long long k = ckey(x, t);
            if (k < prev && k > best) best = k;
        }
        red[threadIdx.x] = best;
        __syncthreads();
        for (int s = BT / 2; s > 0; s >>= 1) {
            if (threadIdx.x < s) {
                unsigned long long o = red[threadIdx.x + s];
                if (o > red[threadIdx.x]) red[threadIdx.x] = o;
            }
            __syncthreads();
        }
        prev = red[0];
        __syncthreads();
    }
    return prev;
}

// K1: PURE streaming pass (measured 79us @ 6.3TB/s). Reads A, zeros out,
// emits bitmask via ballots; first 32 blocks zero g_colcnt.
// Word i*256 + seg*4 + comp, bit b  <->  element (i, seg*128 + b*4 + comp).
__global__ __launch_bounds__(256) void stream_kernel(const float* __restrict__ A,
                                                     float* __restrict__ out) {
    if (blockIdx.x < N / 256) g_colcnt[blockIdx.x * 256 + threadIdx.x] = 0;
    const size_t g = (size_t)blockIdx.x * 256 + threadIdx.x;  // float4 index
    float4 v = ((const float4*)A)[g];
    const float4 zz = {0.0f, 0.0f, 0.0f, 0.0f};
    ((float4*)out)[g] = zz;
    unsigned m0 = __ballot_sync(FULLM, v.x > PIVOT);
    unsigned m1 = __ballot_sync(FULLM, v.y > PIVOT);
    unsigned m2 = __ballot_sync(FULLM, v.z > PIVOT);
    unsigned m3 = __ballot_sync(FULLM, v.w > PIVOT);
    if ((threadIdx.x & 31) == 0) {
        uint4 w = {m0, m1, m2, m3};
        ((uint4*)g_bits)[g >> 5] = w;
    }
}

// K2: block per row. Decode bitmask, gather candidate values once,
// push column candidates (spread atomics), rank-count -> g_rowth.
__global__ __launch_bounds__(256) void rowth_kernel(const float* __restrict__ A) {
    const int i = blockIdx.x, t = threadIdx.x, lane = t & 31, w = t >> 5;
    __shared__ unsigned long long keys[CAP];
    __shared__ int wsum[8];
    __shared__ int s_total;

    unsigned wrd = g_bits[(size_t)i * 256 + t];
    int cnt = __popc(wrd);
    int incl = cnt;
#pragma unroll
    for (int d = 1; d < 32; d <<= 1) {
        int v = __shfl_up_sync(FULLM, incl, d);
        if (lane >= d) incl += v;
    }
    if (lane == 31) wsum[w] = incl;
    __syncthreads();
    if (t == 0) {
        int s = 0;
#pragma unroll
        for (int k = 0; k < 8; k++) { int v = wsum[k]; wsum[k] = s; s += v; }
        s_total = s;
    }
    __syncthreads();
    const int total = s_total;
    int off = incl - cnt + wsum[w];   // exclusive global offset
    const bool ok = (total >= K1 && total <= CAP);

    // decode + gather + column push (always), smem store (if healthy)
    unsigned wb = wrd;
    const int seg = t >> 2, comp = t & 3;
    while (wb) {
        int b = __ffs(wb) - 1;
        wb &= wb - 1;
        int j = seg * 128 + b * 4 + comp;
        float x = A[(size_t)i * N + j];
        if (ok) keys[off] = ckey(x, j);
        off++;
        int cs = atomicAdd(&g_colcnt[j], 1);
        if (cs < CAP) g_colcand[(size_t)j * CAP + cs] = ckey(x, i);
    }
    __syncthreads();

    if (ok) {
        for (int s = t; s < total; s += 256) {
            unsigned long long kt = keys[s];
            int r = 0;
            for (int m = 0; m < total; m++) r += (keys[m] > kt);
            if (r == K1 - 1) g_rowth[i] = kt;   // exactly one writer
        }
    } else {
        unsigned long long th = block_fallback<true, 256>(A, i);
        if (t == 0) g_rowth[i] = th;
    }
}

// K3: block per column. colth by rank-counting its candidate list, then
// scatter survivors in-place. Fallback: exact threshold + full-column rescan.
__global__ __launch_bounds__(128) void colth_scatter_kernel(const float* __restrict__ A,
                                                            float* __restrict__ out) {
    const int j = blockIdx.x, t = threadIdx.x;
    const int c = g_colcnt[j];
    __shared__ unsigned long long cand[CAP];
    __shared__ unsigned long long s_cth;

    if (c >= K1 && c <= CAP) {
        for (int s = t; s < c; s += 128)
            cand[s] = g_colcand[(size_t)j * CAP + s];
        __syncthreads();
        for (int s = t; s < c; s += 128) {
            unsigned long long kt = cand[s];
            int r = 0;
            for (int m = 0; m < c; m++) r += (cand[m] > kt);
            if (r == K1 - 1) s_cth = kt;
        }
        __syncthreads();
        const unsigned long long cth = s_cth;
        for (int s = t; s < c; s += 128) {
            unsigned long long k = cand[s];
            if (k < cth) continue;
            int i = N - 1 - (int)(unsigned int)(k & 0xFFFFFFFFu);
            if (i == j) continue;
            float x = inv_fkey((unsigned int)(k >> 32));
            if (ckey(x, j) >= g_rowth[i])
                out[(size_t)i * N + j] = x;
        }
    } else {
        unsigned long long cth = block_fallback<false, 128>(A, j);
        for (int i = t; i < N; i += 128) {
            if (i == j) continue;
            float x = A[(size_t)i * N + j];
            if (ckey(x, i) >= cth && ckey(x, j) >= g_rowth[i])
                out[(size_t)i * N + j] = x;
        }
    }
}

extern "C" void kernel_launch(void* const* d_in, const int* in_sizes, int n_in,
                              void* d_out, int out_size) {
    const float* A = (const float*)d_in[0];
    float* out = (float*)d_out;
    stream_kernel<<<(unsigned)(NF4 / 256), 256>>>(A, out);
    rowth_kernel<<<N, 256>>>(A);
    colth_scatter_kernel<<<N, 128>>>(A, out);
}